// round 9
// baseline (speedup 1.0000x reference)
#include <cuda_runtime.h>
#include <cuda_fp16.h>
#include <cstdint>
#include <cstddef>

// ---------------- problem constants ----------------
static constexpr int Bb = 64, Tt = 2048, Jj = 128, Dd = 256;
static constexpr int TILE_M = 128;
static constexpr int NT = 512;                 // threads per CTA

// ---------------- smem layout (bytes) ----------------
// Odd-16B row strides make both STS phases and ldmatrix conflict-free:
//   addr = row*STRIDE + col16*16,  col16 = (atomgrp) | ((atom + row) & 7)
static constexpr int BSTRIDE = 528;            // 256 halves + 16B rotate
static constexpr int ASTRIDE = 144;            // 64 halves + 16B rotate
static constexpr int SM_W  = 0;                // 768 f32
static constexpr int SM_SH = 3072;             // 128 f32
static constexpr int SM_SU = 3584;             // 128 f32 (ends 4096)
static constexpr int SM_B  = 4096;             // 128*528 = 67584
static constexpr int SM_A0 = SM_B + 128 * BSTRIDE;      // 71680
static constexpr int SM_A1 = SM_A0 + 128 * ASTRIDE;     // 90112
static constexpr int SMEM_BYTES = SM_A1 + 128 * ASTRIDE; // 108544

// ---------------- helpers ----------------
__device__ __forceinline__ uint32_t smem_u32(const void* p) {
    uint32_t a;
    asm("{ .reg .u64 t; cvta.to.shared.u64 t, %1; cvt.u32.u64 %0, t; }"
        : "=r"(a) : "l"(p));
    return a;
}

__device__ __forceinline__ uint32_t pk(float a, float b) {
    __half2 h = __floats2half2_rn(a, b);
    return *reinterpret_cast<uint32_t*>(&h);
}

__device__ __forceinline__ void ldm_x4(uint32_t* r, uint32_t addr) {
    asm volatile("ldmatrix.sync.aligned.m8n8.x4.shared.b16 {%0,%1,%2,%3}, [%4];"
                 : "=r"(r[0]), "=r"(r[1]), "=r"(r[2]), "=r"(r[3])
                 : "r"(addr));
}

__device__ __forceinline__ void mma16816(float* c, const uint32_t* a,
                                         const uint32_t* b) {
    asm volatile(
        "mma.sync.aligned.m16n8k16.row.col.f32.f16.f16.f32 "
        "{%0,%1,%2,%3}, {%4,%5,%6,%7}, {%8,%9}, {%0,%1,%2,%3};"
        : "+f"(c[0]), "+f"(c[1]), "+f"(c[2]), "+f"(c[3])
        : "r"(a[0]), "r"(a[1]), "r"(a[2]), "r"(a[3]), "r"(b[0]), "r"(b[1]));
}

// ---------------- kernel ----------------
__global__ void __launch_bounds__(NT, 1)
sim_kernel(const float* __restrict__ H, const float* __restrict__ U,
           const float* __restrict__ w, float* __restrict__ out) {
    extern __shared__ char smem[];
    const uint32_t sb = smem_u32(smem);
    float* ws  = (float*)(smem + SM_W);
    float* shs = (float*)(smem + SM_SH);
    float* sus = (float*)(smem + SM_SU);

    const int tid = threadIdx.x;
    const int wid = tid >> 5, lid = tid & 31;
    const int b   = blockIdx.x >> 4;
    const int t0  = (blockIdx.x & 15) * TILE_M;
    const float* Ub = U + (size_t)b * Jj * Dd;
    const float* Hb = H + ((size_t)b * Tt + t0) * Dd;

    for (int i = tid; i < 3 * Dd; i += NT) ws[i] = w[i];
    __syncthreads();
    const float* w1s = ws;
    const float* w2s = ws + Dd;
    const float* w3s = ws + 2 * Dd;

    // chunk-load mapping: 128 rows x 64 cols per chunk, 16 floats/thread
    const int row = tid >> 2;      // 0..127
    const int t4  = tid & 3;       // 16-float segment within 64-col chunk

    float su_p = 0.f, sh_p = 0.f;  // per-thread partial dots
    float4 preU[4], preH[4];

    // ---- chunk-phase lambdas (manual) ----
    // ldg: issue 4 LDG.128 each for U and H chunk c
#define LDG_U(c) { const float* p = Ub + (size_t)row * Dd + (c) * 64 + t4 * 16; \
    preU[0] = *(const float4*)(p);     preU[1] = *(const float4*)(p + 4);       \
    preU[2] = *(const float4*)(p + 8); preU[3] = *(const float4*)(p + 12); }
#define LDG_H(c) { const float* p = Hb + (size_t)row * Dd + (c) * 64 + t4 * 16; \
    preH[0] = *(const float4*)(p);     preH[1] = *(const float4*)(p + 4);       \
    preH[2] = *(const float4*)(p + 8); preH[3] = *(const float4*)(p + 12); }

    // sts U chunk c: fp16 convert + fused s_u partial (U . w2)
#define STS_U(c) {                                                              \
    _Pragma("unroll")                                                           \
    for (int h = 0; h < 2; h++) {                                               \
        const int k = (c) * 64 + t4 * 16 + h * 8;                               \
        const float4 v0 = preU[h * 2], v1 = preU[h * 2 + 1];                    \
        const float4 q0 = *(const float4*)(w2s + k);                            \
        const float4 q1 = *(const float4*)(w2s + k + 4);                        \
        su_p += v0.x * q0.x + v0.y * q0.y + v0.z * q0.z + v0.w * q0.w +         \
                v1.x * q1.x + v1.y * q1.y + v1.z * q1.z + v1.w * q1.w;          \
        uint4 hv;                                                               \
        hv.x = pk(v0.x, v0.y); hv.y = pk(v0.z, v0.w);                           \
        hv.z = pk(v1.x, v1.y); hv.w = pk(v1.z, v1.w);                           \
        const int a = (c) * 8 + t4 * 2 + h;                                     \
        *(uint4*)(smem + SM_B + row * BSTRIDE +                                 \
                  (((a & 24) | ((a + row) & 7)) << 4)) = hv;                    \
    } }

    // sts H chunk c into buf: w3-scale + fp16 + fused s_h partial (H . w1)
#define STS_H(c, base) {                                                        \
    _Pragma("unroll")                                                           \
    for (int h = 0; h < 2; h++) {                                               \
        const int k = (c) * 64 + t4 * 16 + h * 8;                               \
        const float4 v0 = preH[h * 2], v1 = preH[h * 2 + 1];                    \
        const float4 q0 = *(const float4*)(w1s + k);                            \
        const float4 q1 = *(const float4*)(w1s + k + 4);                        \
        const float4 r0 = *(const float4*)(w3s + k);                            \
        const float4 r1 = *(const float4*)(w3s + k + 4);                        \
        sh_p += v0.x * q0.x + v0.y * q0.y + v0.z * q0.z + v0.w * q0.w +         \
                v1.x * q1.x + v1.y * q1.y + v1.z * q1.z + v1.w * q1.w;          \
        uint4 hv;                                                               \
        hv.x = pk(v0.x * r0.x, v0.y * r0.y);                                    \
        hv.y = pk(v0.z * r0.z, v0.w * r0.w);                                    \
        hv.z = pk(v1.x * r1.x, v1.y * r1.y);                                    \
        hv.w = pk(v1.z * r1.z, v1.w * r1.w);                                    \
        const int a = t4 * 2 + h;                                               \
        *(uint4*)(smem + (base) + row * ASTRIDE + (((a + row) & 7) << 4)) = hv; \
    } }

    // ---- prologue: chunk 0 ----
    LDG_U(0); LDG_H(0);
    STS_U(0); STS_H(0, SM_A0);
    __syncthreads();

    // ---- mainloop: 4x4 warp grid, 32x32 warp tile ----
    const int wm = (wid & 3) * 32;
    const int wn = (wid >> 2) * 32;
    float acc[2][4][4];
#pragma unroll
    for (int mt = 0; mt < 2; mt++)
#pragma unroll
        for (int nt = 0; nt < 4; nt++)
#pragma unroll
            for (int r = 0; r < 4; r++) acc[mt][nt][r] = 0.f;

    for (int c = 0; c < 4; c++) {
        if (c < 3) { LDG_U(c + 1); LDG_H(c + 1); }   // LDGs fly under MMA
        const uint32_t abase = sb + ((c & 1) ? SM_A1 : SM_A0);
#pragma unroll
        for (int k16 = 0; k16 < 4; k16++) {
            uint32_t af[2][4];
#pragma unroll
            for (int mt = 0; mt < 2; mt++) {
                const int r = wm + mt * 16 + (lid & 15);
                const int a = k16 * 2 + (lid >> 4);
                ldm_x4(af[mt], abase + r * ASTRIDE + (((a + r) & 7) << 4));
            }
            uint32_t bf[4][2];
#pragma unroll
            for (int nt2 = 0; nt2 < 2; nt2++) {
                const int n = wn + nt2 * 16 + ((lid >> 4) << 3) + (lid & 7);
                const int a = c * 8 + k16 * 2 + ((lid >> 3) & 1);
                uint32_t r[4];
                ldm_x4(r, sb + SM_B + n * BSTRIDE +
                              (((a & 24) | ((a + n) & 7)) << 4));
                bf[nt2 * 2][0] = r[0]; bf[nt2 * 2][1] = r[1];
                bf[nt2 * 2 + 1][0] = r[2]; bf[nt2 * 2 + 1][1] = r[3];
            }
#pragma unroll
            for (int mt = 0; mt < 2; mt++)
#pragma unroll
                for (int nt = 0; nt < 4; nt++)
                    mma16816(acc[mt][nt], af[mt], bf[nt]);
        }
        if (c < 3) {
            STS_U(c + 1);
            STS_H(c + 1, (((c + 1) & 1) ? SM_A1 : SM_A0));
            __syncthreads();
        }
    }

    // ---- s_u / s_h reduce (4 lanes per row) + publish ----
    {
        float r = su_p;
        r += __shfl_xor_sync(0xffffffffu, r, 1);
        r += __shfl_xor_sync(0xffffffffu, r, 2);
        if (t4 == 0) sus[row] = r;
        float s = sh_p;
        s += __shfl_xor_sync(0xffffffffu, s, 1);
        s += __shfl_xor_sync(0xffffffffu, s, 2);
        if (t4 == 0) shs[row] = s;
    }
    __syncthreads();

    // ---- epilogue: acc + s_h[m] + s_u[n] -> out ----
    float* outp = out + ((size_t)b * Tt + t0) * Jj;
#pragma unroll
    for (int mt = 0; mt < 2; mt++) {
        const int m0 = wm + mt * 16 + (lid >> 2);
        const float sh0 = shs[m0];
        const float sh1 = shs[m0 + 8];
#pragma unroll
        for (int nt = 0; nt < 4; nt++) {
            const int n = wn + nt * 8 + (lid & 3) * 2;
            const float2 su = *(const float2*)(sus + n);
            float2 o0, o1;
            o0.x = acc[mt][nt][0] + sh0 + su.x;
            o0.y = acc[mt][nt][1] + sh0 + su.y;
            o1.x = acc[mt][nt][2] + sh1 + su.x;
            o1.y = acc[mt][nt][3] + sh1 + su.y;
            *(float2*)(outp + (size_t)m0 * Jj + n) = o0;
            *(float2*)(outp + (size_t)(m0 + 8) * Jj + n) = o1;
        }
    }
}

// ---------------- launch ----------------
extern "C" void kernel_launch(void* const* d_in, const int* in_sizes, int n_in,
                              void* d_out, int out_size) {
    const float* H = (const float*)d_in[0];
    const float* U = (const float*)d_in[1];
    const float* w = (const float*)d_in[2];
    float* out = (float*)d_out;

    cudaFuncSetAttribute(sim_kernel, cudaFuncAttributeMaxDynamicSharedMemorySize,
                         SMEM_BYTES);
    sim_kernel<<<Bb * (Tt / TILE_M), NT, SMEM_BYTES>>>(H, U, w, out);
}